// round 10
// baseline (speedup 1.0000x reference)
#include <cuda_runtime.h>

// Problem constants
#define BB 65536
#define DD 256
#define KK 32
#define TM 64
#define NBLK (BB / TM)   // 1024
#define BD (BB * DD)

// Device scratch (no cudaMalloc allowed)
__device__ float g_G1[KK * KK];                    // W . U^T
__device__ float g_G2[KK * KK];                    // W . W^T
__device__ __align__(16) float g_uhat[KK * DD];    // [k][d]
__device__ __align__(16) float g_WT[DD * KK];      // W transposed [d][k]

// ---------- f32x2 helpers ----------
__device__ __forceinline__ unsigned long long ffma2(unsigned long long a,
                                                    unsigned long long b,
                                                    unsigned long long c) {
    unsigned long long d;
    asm("fma.rn.f32x2 %0, %1, %2, %3;" : "=l"(d) : "l"(a), "l"(b), "l"(c));
    return d;
}
__device__ __forceinline__ unsigned long long packf2(float x, float y) {
    unsigned long long r;
    asm("mov.b64 %0, {%1, %2};" : "=l"(r) : "f"(x), "f"(y));
    return r;
}

// fast accurate tanh: 1 - 2/(exp(2x)+1)
__device__ __forceinline__ float ftanh(float x) {
    float e = __expf(2.0f * x);
    return 1.0f - __fdividef(2.0f, e + 1.0f);
}

__device__ __forceinline__ float softplus(float x) {
    return fmaxf(x, 0.f) + log1pf(expf(-fabsf(x)));
}

// ---------- Gram kernel: G1[k][:], G2[k][:], uhat_k, W^T  (block = k) ----------
__global__ __launch_bounds__(256, 4)
void k_gram(const float* __restrict__ u, const float* __restrict__ w) {
    __shared__ float ws[DD];
    __shared__ float sdiag[2];
    const int k = blockIdx.x, t = threadIdx.x;
    ws[t] = w[k * DD + t];
    __syncthreads();

    // W^T for broadcast loads in nf_main phase 1
    g_WT[t * KK + k] = ws[t];

    const int j = t >> 3, s = t & 7;
    {
        const float* up  = u + j * DD + s * 32;
        const float* wp2 = w + j * DD + s * 32;
        const float* wsp = ws + s * 32;
        float p1 = 0.f, p2 = 0.f;
        #pragma unroll
        for (int i = 0; i < 32; ++i) {
            float wv = wsp[i];
            p1 = fmaf(wv, up[i], p1);
            p2 = fmaf(wv, wp2[i], p2);
        }
        #pragma unroll
        for (int o = 1; o <= 4; o <<= 1) {
            p1 += __shfl_xor_sync(0xffffffffu, p1, o);
            p2 += __shfl_xor_sync(0xffffffffu, p2, o);
        }
        if (s == 0) {
            g_G1[k * KK + j] = p1;
            g_G2[k * KK + j] = p2;
            if (j == k) { sdiag[0] = p1; sdiag[1] = p2; }
        }
    }
    __syncthreads();

    float wu = sdiag[0], ww = sdiag[1];
    float alpha = (softplus(wu) - 1.0f - wu) / ww;
    g_uhat[k * DD + t] = fmaf(alpha, ws[t], u[k * DD + t]);
}

// ---------- Main monolith ----------
// smem (floats):
//  XS : 0      X tile [r][d] stride 260 (float4-clean)         = 16640
//  CP : 16640  partial C, 2 d-halves x [r(stride34)][k]        = 4352
//              (half 0 becomes the reduced C = CS)
//  TS : 20992  t [r][k] stride 36 (float4 reads)               = 2304
//  AS : 23296  A[k][j]                                         = 1024
//  AL : 24320  alpha[32]
//  BS : 24352  b[32]
// total 24384 floats = 97536 B -> 2 blocks/SM, ~33KB L1D left
#define OFF_XS 0
#define OFF_CP 16640
#define OFF_TS 20992
#define OFF_AS 23296
#define OFF_AL 24320
#define OFF_BS 24352
#define SMEM_FLOATS 24384

__global__ __launch_bounds__(256, 2)
void nf_main(const float* __restrict__ X, const float* __restrict__ bvec,
             float* __restrict__ out) {
    extern __shared__ float sm[];
    float* XS = sm + OFF_XS;
    float* CP = sm + OFF_CP;   // CS aliases CP half 0
    float* TS = sm + OFF_TS;
    float* AS = sm + OFF_AS;
    float* AL = sm + OFF_AL;
    float* BS = sm + OFF_BS;

    const int t = threadIdx.x;
    const int r0 = blockIdx.x * TM;

    // ---- Prologue: stage X (float4, conflict-free), alpha, b ----
    {
        const float4* Xb4 = (const float4*)(X + (size_t)r0 * DD);
        #pragma unroll
        for (int i = t; i < TM * DD / 4; i += 256) {
            int r = i >> 6, d4 = i & 63;
            *(float4*)&XS[r * 260 + d4 * 4] = Xb4[i];
        }
        if (t < KK) {
            float wu = g_G1[t * (KK + 1)];
            float ww = g_G2[t * (KK + 1)];
            AL[t] = (softplus(wu) - 1.0f - wu) / ww;
            BS[t] = bvec[t];
        }
    }
    __syncthreads();

    // A = G1 + alpha_j * G2 (consumed after a later barrier)
    #pragma unroll
    for (int e = t; e < KK * KK; e += 256)
        AS[e] = g_G1[e] + AL[e & 31] * g_G2[e];

    // ---- Phase 1: partial C = X . W^T ----
    // warp = (d-half dh, k-group kg of 8); lane = rows lane, lane+32
    {
        const int wp = t >> 5, lane = t & 31;
        const int dh = wp >> 2, kg = wp & 3;
        const int k0 = kg * 8;
        const int d0 = dh * 128;
        unsigned long long c0[4], c1[4];
        #pragma unroll
        for (int q = 0; q < 4; ++q) { c0[q] = 0ull; c1[q] = 0ull; }
        const float* x0p = XS + lane * 260 + d0;
        const float* x1p = XS + (lane + 32) * 260 + d0;
        #pragma unroll 8
        for (int dd = 0; dd < 128; dd += 4) {
            float4 xa = *(const float4*)(x0p + dd);
            float4 xb = *(const float4*)(x1p + dd);
            #pragma unroll
            for (int j = 0; j < 4; ++j) {
                const longlong2 wa = __ldg((const longlong2*)&g_WT[(d0 + dd + j) * KK + k0]);
                const longlong2 wb = __ldg((const longlong2*)&g_WT[(d0 + dd + j) * KK + k0 + 4]);
                float xj0 = (&xa.x)[j];
                float xj1 = (&xb.x)[j];
                unsigned long long p0 = packf2(xj0, xj0);
                unsigned long long p1 = packf2(xj1, xj1);
                c0[0] = ffma2(p0, (unsigned long long)wa.x, c0[0]);
                c0[1] = ffma2(p0, (unsigned long long)wa.y, c0[1]);
                c0[2] = ffma2(p0, (unsigned long long)wb.x, c0[2]);
                c0[3] = ffma2(p0, (unsigned long long)wb.y, c0[3]);
                c1[0] = ffma2(p1, (unsigned long long)wa.x, c1[0]);
                c1[1] = ffma2(p1, (unsigned long long)wa.y, c1[1]);
                c1[2] = ffma2(p1, (unsigned long long)wb.x, c1[2]);
                c1[3] = ffma2(p1, (unsigned long long)wb.y, c1[3]);
            }
        }
        float* cp = CP + dh * 2176;
        #pragma unroll
        for (int q = 0; q < 4; ++q) {
            *(unsigned long long*)&cp[lane * 34 + k0 + 2 * q]        = c0[q];
            *(unsigned long long*)&cp[(lane + 32) * 34 + k0 + 2 * q] = c1[q];
        }
    }
    __syncthreads();

    // ---- Reduce the 2 d-halves into CP half 0 (= CS) ----
    #pragma unroll
    for (int e = t; e < TM * KK; e += 256) {
        int row = e >> 5, k = e & 31;
        int idx = row * 34 + k;
        CP[idx] += CP[2176 + idx];
    }
    __syncthreads();

    // ---- Phase 2: triangular recurrence, thread = row (t < 64) ----
    if (t < TM) {
        const int row = t;
        float tl[KK];
        #pragma unroll
        for (int k = 0; k < KK; ++k) {
            float lin = CP[row * 34 + k] + BS[k];
            #pragma unroll
            for (int j = 0; j < k; ++j)
                lin = fmaf(AS[k * KK + j], tl[j], lin);
            float tk = ftanh(lin);
            tl[k] = tk;
            TS[row * 36 + k] = tk;
            float akk = AS[k * (KK + 1)];
            out[BD + k * BB + r0 + row] =
                __logf(fabsf(fmaf(1.0f - tk * tk, akk, 1.0f)) + 1e-8f);
        }
    }
    __syncthreads();

    // ---- Phase 3: Z = X + T . Uhat (uhat via coalesced LDG broadcasts) ----
    {
        const int lane = t & 31, wp = t >> 5;
        const int c0 = lane * 4, c1 = 128 + lane * 4;
        #pragma unroll
        for (int g = 0; g < 2; ++g) {
            const int rb = wp * 8 + g * 4;
            ulonglong2 a[4][2];
            #pragma unroll
            for (int r = 0; r < 4; ++r) {
                a[r][0] = *(const ulonglong2*)&XS[(rb + r) * 260 + c0];
                a[r][1] = *(const ulonglong2*)&XS[(rb + r) * 260 + c1];
            }
            #pragma unroll
            for (int kc = 0; kc < 8; ++kc) {
                float4 tv[4];
                #pragma unroll
                for (int r = 0; r < 4; ++r)
                    tv[r] = *(const float4*)&TS[(rb + r) * 36 + kc * 4];
                #pragma unroll
                for (int kk = 0; kk < 4; ++kk) {
                    const int k = kc * 4 + kk;
                    const longlong2 u0 = __ldg((const longlong2*)&g_uhat[k * DD + c0]);
                    const longlong2 u1 = __ldg((const longlong2*)&g_uhat[k * DD + c1]);
                    #pragma unroll
                    for (int r = 0; r < 4; ++r) {
                        float ts = (&tv[r].x)[kk];
                        unsigned long long tt = packf2(ts, ts);
                        a[r][0].x = ffma2(tt, (unsigned long long)u0.x, a[r][0].x);
                        a[r][0].y = ffma2(tt, (unsigned long long)u0.y, a[r][0].y);
                        a[r][1].x = ffma2(tt, (unsigned long long)u1.x, a[r][1].x);
                        a[r][1].y = ffma2(tt, (unsigned long long)u1.y, a[r][1].y);
                    }
                }
            }
            #pragma unroll
            for (int r = 0; r < 4; ++r) {
                float* zr = out + (size_t)(r0 + rb + r) * DD;
                *(ulonglong2*)(zr + c0) = a[r][0];
                *(ulonglong2*)(zr + c1) = a[r][1];
            }
        }
    }
}

extern "C" void kernel_launch(void* const* d_in, const int* in_sizes, int n_in,
                              void* d_out, int out_size) {
    const float* X = (const float*)d_in[0];
    // d_in[1] = h (unused)
    const float* u = (const float*)d_in[2];
    const float* w = (const float*)d_in[3];
    const float* b = (const float*)d_in[4];
    float* out = (float*)d_out;

    cudaFuncSetAttribute(nf_main, cudaFuncAttributeMaxDynamicSharedMemorySize,
                         SMEM_FLOATS * (int)sizeof(float));

    k_gram<<<KK, 256>>>(u, w);
    nf_main<<<NBLK, 256, SMEM_FLOATS * sizeof(float)>>>(X, b, out);
}